// round 15
// baseline (speedup 1.0000x reference)
#include <cuda_runtime.h>
#include <cuda_fp16.h>
#include <cstdint>

// Problem dims: B=8, T=2048 -> N=16384 tokens, D=512, E=8, H=1024, top_k=2
#define N_TOK   16384
#define D_DIM   512
#define E_EXP   8
#define H_DIM   1024
#define NPAIR   (2 * N_TOK)
#define RBLK    (N_TOK / 8)
#define CAP     N_TOK                 // fixed per-expert segment capacity
#define NROW    (E_EXP * CAP)

#define BN 128
#define KCH 64                       // 64 fp16 = 128B data per row per chunk
#define ROWB 144                     // smem row stride (128B data + 16B pad)
#define NSTAGE 3
#define MAXT1 264                    // pass1 tile grid (BM=128)
#define MAXT2 520                    // pass2 tile grid (BM=64)

// ---------------- scratch (static device globals) ----------------
__device__ __align__(1024) __half g_xq[(size_t)N_TOK * D_DIM];
__device__ __align__(1024) __half g_w1q[(size_t)E_EXP * H_DIM * D_DIM]; // [E][H][D] K-major
__device__ __align__(1024) __half g_w2q[(size_t)E_EXP * D_DIM * H_DIM]; // [E][D][H] K-major
__device__ __align__(1024) __half g_hq[(size_t)NROW * H_DIM];
__device__ __align__(1024) float g_out2[(size_t)NROW * D_DIM];
__device__ int   g_tok[NROW];
__device__ float g_w[NROW];
__device__ int   g_slot[NPAIR];
__device__ int   g_cnt[E_EXP];                   // zeroed at load; re-zeroed by combine tail
__device__ int   g_done;                         // router completion ticket (reset by elected block)
__device__ int   g_toff1[E_EXP + 1];             // tile prefix, BM=128 (pass1)
__device__ int   g_toff2[E_EXP + 1];             // tile prefix, BM=64  (pass2)
__device__ float g_psums[RBLK * E_EXP];

// ---------------- PTX helpers (baseline ISA only) ----------------
__device__ __forceinline__ uint32_t smem_u32(const void* p) {
    uint32_t a;
    asm("{ .reg .u64 t; cvta.to.shared.u64 t, %1; cvt.u32.u64 %0, t; }" : "=r"(a) : "l"(p));
    return a;
}
__device__ __forceinline__ void cp16(uint32_t dst, const void* src) {
    asm volatile("cp.async.cg.shared.global [%0], [%1], 16;" :: "r"(dst), "l"(src));
}
__device__ __forceinline__ void ldsm4(uint32_t* r, uint32_t addr) {
    asm volatile("ldmatrix.sync.aligned.m8n8.x4.shared.b16 {%0,%1,%2,%3}, [%4];"
                 : "=r"(r[0]), "=r"(r[1]), "=r"(r[2]), "=r"(r[3]) : "r"(addr));
}
__device__ __forceinline__ void mma_f16(float* c, const uint32_t* a, uint32_t b0, uint32_t b1) {
    asm volatile(
        "mma.sync.aligned.m16n8k16.row.col.f32.f16.f16.f32 "
        "{%0,%1,%2,%3}, {%4,%5,%6,%7}, {%8,%9}, {%0,%1,%2,%3};"
        : "+f"(c[0]), "+f"(c[1]), "+f"(c[2]), "+f"(c[3])
        : "r"(a[0]), "r"(a[1]), "r"(a[2]), "r"(a[3]), "r"(b0), "r"(b1));
}

// ---------------- router (fused: logits+softmax+top2+scatter+x->fp16+prefix+loss) ----------------
__global__ void router_kernel(const float* __restrict__ x,
                              const float* __restrict__ Wr,
                              const float* __restrict__ br,
                              float* __restrict__ out, int out_size) {
    __shared__ float ps[8][E_EXP];
    __shared__ float dsq[E_EXP];
    __shared__ int is_last;
    const int wid = threadIdx.x >> 5, lane = threadIdx.x & 31;
    const int n = blockIdx.x * 8 + wid;
    const float* xr = x + (size_t)n * D_DIM;
    __half* xq = g_xq + (size_t)n * D_DIM;
    float acc[E_EXP];
#pragma unroll
    for (int e = 0; e < E_EXP; e++) acc[e] = 0.f;
    for (int i = lane; i < D_DIM; i += 32) {       // coalesced on x (proven layout)
        float xv = xr[i];
        xq[i] = __float2half_rn(xv);
        const float* w = Wr + i * E_EXP;
#pragma unroll
        for (int e = 0; e < E_EXP; e++) acc[e] += xv * w[e];
    }
#pragma unroll
    for (int e = 0; e < E_EXP; e++)
#pragma unroll
        for (int o = 16; o > 0; o >>= 1)
            acc[e] += __shfl_xor_sync(0xffffffffu, acc[e], o);

    if (lane == 0) {
        float mx = -1e30f;
#pragma unroll
        for (int e = 0; e < E_EXP; e++) { acc[e] += br[e]; mx = fmaxf(mx, acc[e]); }
        float s = 0.f;
#pragma unroll
        for (int e = 0; e < E_EXP; e++) { acc[e] = expf(acc[e] - mx); s += acc[e]; }
        const float inv = 1.f / s;
        float p1 = -1.f, p2 = -1.f; int i1 = 0, i2 = 0;
#pragma unroll
        for (int e = 0; e < E_EXP; e++) {
            float p = acc[e] * inv;
            ps[wid][e] = p;
            if (p > p1)      { p2 = p1; i2 = i1; p1 = p; i1 = e; }
            else if (p > p2) { p2 = p; i2 = e; }
        }
        int pos1 = atomicAdd(&g_cnt[i1], 1);
        int p1i = i1 * CAP + pos1;
        g_tok[p1i] = n; g_w[p1i] = p1; g_slot[2 * n] = p1i;
        int pos2 = atomicAdd(&g_cnt[i2], 1);
        int p2i = i2 * CAP + pos2;
        g_tok[p2i] = n; g_w[p2i] = p2; g_slot[2 * n + 1] = p2i;
    }
    __syncthreads();
    if (threadIdx.x < E_EXP) {
        float s = 0.f;
#pragma unroll
        for (int w = 0; w < 8; w++) s += ps[w][threadIdx.x];
        g_psums[blockIdx.x * E_EXP + threadIdx.x] = s;
    }
    __syncthreads();
    if (threadIdx.x == 0) {
        __threadfence();
        is_last = (atomicAdd(&g_done, 1) == RBLK - 1) ? 1 : 0;
    }
    __syncthreads();
    if (!is_last) return;

    // ---- elected last block: tile prefixes + gating loss ----
    if (threadIdx.x == 0) {
        g_done = 0;                                // reset for next replay
        int t1 = 0, t2 = 0;
        for (int e = 0; e < E_EXP; e++) {
            g_toff1[e] = t1;
            g_toff2[e] = t2;
            int c = g_cnt[e];
            t1 += (c + 127) >> 7;
            t2 += (c + 63) >> 6;
        }
        g_toff1[E_EXP] = t1;
        g_toff2[E_EXP] = t2;
    }
    if (wid < E_EXP) {
        float s = 0.f;
        for (int b = lane; b < RBLK; b += 32) s += g_psums[b * E_EXP + wid];
#pragma unroll
        for (int o = 16; o > 0; o >>= 1) s += __shfl_xor_sync(0xffffffffu, s, o);
        if (lane == 0) {
            float mean = s / (float)N_TOK;
            float d = (1.0f / E_EXP) - mean;
            dsq[wid] = d * d;
        }
    }
    __syncthreads();
    if (threadIdx.x == 0 && out_size > N_TOK * D_DIM) {
        float l = 0.f;
        for (int e = 0; e < E_EXP; e++) l += dsq[e];
        out[N_TOK * D_DIM] = (l / E_EXP) * 1e-4f;
    }
}

// ---------------- merged weight transpose (real device addrs only — ATS trap) ----------------
__global__ void transpose_both_kernel(const float* __restrict__ W1,
                                      const float* __restrict__ W2,
                                      __half* __restrict__ T1,
                                      __half* __restrict__ T2) {
    __shared__ float t[32][33];
    const int z = blockIdx.z;
    const bool isW2 = (z >= E_EXP);
    const int e = z & (E_EXP - 1);
    const int K = isW2 ? H_DIM : D_DIM;
    const int N = isW2 ? D_DIM : H_DIM;
    const float* W = isW2 ? W2 : W1;
    __half* T = isW2 ? T2 : T1;
    const int n0 = blockIdx.x * 32, k0 = blockIdx.y * 32;
    if (n0 >= N || k0 >= K) return;
    const int tx = threadIdx.x, ty = threadIdx.y;
    for (int i = ty; i < 32; i += 8)
        t[i][tx] = W[((size_t)e * K + k0 + i) * N + n0 + tx];
    __syncthreads();
    for (int i = ty; i < 32; i += 8) {
        float v = t[tx][i];
        T[((size_t)e * N + n0 + i) * K + k0 + tx] = __float2half_rn(v);
    }
}

// ---------------- fp16 GEMM via mma.m16n8k16 + ldmatrix ----------------
// PASS2=false: BM=128, h = leaky(gather(xq)@W1q^T + b1) -> g_hq,   KDIM=512,  NCOL=1024
// PASS2=true : BM=64,  o = w*leaky(hq@W2q^T + b2)       -> g_out2, KDIM=1024, NCOL=512
template <bool PASS2, int KDIM, int NCOL>
__global__ void __launch_bounds__(256, 2)
gemm_f16(const float* __restrict__ bias) {
    constexpr int BMT = PASS2 ? 64 : 128;        // m-tile
    constexpr int MH  = BMT / 2;                 // rows per warp_m
    constexpr int AF  = MH / 16;                 // a-frags per warp (4 / 2)
    constexpr int AU  = BMT * 8 / 256;           // A cp.async units/thread (4 / 2)
    constexpr int TILE_A = BMT * ROWB;
    constexpr int TILE_B = BN * ROWB;
    constexpr int STG = TILE_A + TILE_B;

    extern __shared__ char smem[];
    const int* toff = PASS2 ? g_toff2 : g_toff1;
    const int ty = blockIdx.y;
    if (ty >= toff[E_EXP]) return;
    int e = 0;
#pragma unroll
    for (int i = 1; i < E_EXP; i++) if (ty >= toff[i]) e = i;
    const int cnt = g_cnt[e];
    const int m0 = (ty - toff[e]) * BMT;
    const int n0 = blockIdx.x * BN;
    const int off = e * CAP;
    const int tid = threadIdx.x;
    const int wid = tid >> 5, lane = tid & 31;
    const int warp_m = wid >> 2;                 // 0..1
    const int warp_n = wid & 3;                  // 0..3 (32 cols each)
    const int qr = lane >> 2;
    const int qc = (lane & 3) * 2;

    const uint32_t sbase = smem_u32(smem);
    int* toks = (int*)smem;                      // [0,512)
    const uint32_t TILE0 = 1024;

    if (!PASS2) {
        if (tid < BMT) {
            int m = m0 + tid;
            toks[tid] = g_tok[off + (m < cnt ? m : cnt - 1)];
        }
        __syncthreads();
    }

    const char* Aqb = (const char*)(PASS2 ? g_hq : g_xq);
    const char* Bqb = (const char*)(PASS2 ? g_w2q : g_w1q);

    // cp.async plan
    size_t aoff[AU], boff[4];
    uint32_t adst[AU], bdst[4];
#pragma unroll
    for (int t = 0; t < AU; t++) {
        int uu = tid + 256 * t;
        int r = uu >> 3, u = uu & 7;
        adst[t] = (uint32_t)(r * ROWB + u * 16);
        if (!PASS2) {
            aoff[t] = ((size_t)toks[r] * KDIM) * 2 + u * 16;
        } else {
            int m = m0 + r;
            int row = off + (m < cnt ? m : cnt - 1);
            aoff[t] = ((size_t)row * KDIM) * 2 + u * 16;
        }
    }
#pragma unroll
    for (int t = 0; t < 4; t++) {
        int uu = tid + 256 * t;
        int r = uu >> 3, u = uu & 7;
        bdst[t] = (uint32_t)(r * ROWB + u * 16);
        boff[t] = ((size_t)(e * NCOL + n0 + r) * KDIM) * 2 + u * 16;
    }

    auto issue_loads = [&](int c, int s) {
        const uint32_t st = sbase + TILE0 + s * STG;
        const size_t kb = (size_t)c * (KCH * 2);
#pragma unroll
        for (int t = 0; t < AU; t++)
            cp16(st + adst[t], Aqb + aoff[t] + kb);
#pragma unroll
        for (int t = 0; t < 4; t++)
            cp16(st + TILE_A + bdst[t], Bqb + boff[t] + kb);
        asm volatile("cp.async.commit_group;" ::: "memory");
    };

    float acc[AF][4][4];
#pragma unroll
    for (int f = 0; f < AF; f++)
#pragma unroll
        for (int g = 0; g < 4; g++)
#pragma unroll
            for (int q = 0; q < 4; q++) acc[f][g][q] = 0.f;

    constexpr int C = KDIM / KCH;
    issue_loads(0, 0);
    issue_loads(1, 1);

    uint32_t aBase[AF];
#pragma unroll
    for (int f = 0; f < AF; f++)
        aBase[f] = (uint32_t)((warp_m * MH + f * 16 + (lane & 15)) * ROWB + (lane >> 4) * 16);
    uint32_t bBase[2];
#pragma unroll
    for (int p = 0; p < 2; p++)
        bBase[p] = (uint32_t)((warp_n * 32 + p * 16 + ((lane >> 4) & 1) * 8 + (lane & 7)) * ROWB
                              + ((lane >> 3) & 1) * 16);

    for (int c = 0; c < C; c++) {
        const int s = c % NSTAGE;
        if (c == C - 1) asm volatile("cp.async.wait_group 0;" ::: "memory");
        else            asm volatile("cp.async.wait_group 1;" ::: "memory");
        __syncthreads();                         // single barrier per chunk
        if (c + 2 < C) issue_loads(c + 2, (c + 2) % NSTAGE);

        const uint32_t stA = sbase + TILE0 + s * STG;
        const uint32_t stB = stA + TILE_A;

#pragma unroll
        for (int ks = 0; ks < 4; ks++) {
            const uint32_t ko = (uint32_t)(ks * 32);
            uint32_t aq[AF][4], bq[2][4];
#pragma unroll
            for (int f = 0; f < AF; f++) ldsm4(aq[f], stA + aBase[f] + ko);
#pragma unroll
            for (int p = 0; p < 2; p++) ldsm4(bq[p], stB + bBase[p] + ko);
#pragma unroll
            for (int f = 0; f < AF; f++)
#pragma unroll
                for (int p = 0; p < 2; p++) {
                    mma_f16(acc[f][2 * p],     aq[f], bq[p][0], bq[p][1]);
                    mma_f16(acc[f][2 * p + 1], aq[f], bq[p][2], bq[p][3]);
                }
        }
    }

    // ---- epilogue ----
    const float* bb = bias + e * NCOL + n0;
#pragma unroll
    for (int f = 0; f < AF; f++) {
        const int rbase = warp_m * MH + f * 16 + qr;
#pragma unroll
        for (int half = 0; half < 2; half++) {
            const int row = rbase + half * 8;
            const int m = m0 + row;
            if (m >= cnt) continue;
            const int grow = off + m;
            float wgt = 0.f;
            if (PASS2) wgt = g_w[grow];
#pragma unroll
            for (int g = 0; g < 4; g++) {
                const int col = warp_n * 32 + g * 8 + qc;
                float v0 = acc[f][g][2 * half + 0] + bb[col];
                float v1 = acc[f][g][2 * half + 1] + bb[col + 1];
                v0 = (v0 > 0.f) ? v0 : 0.01f * v0;
                v1 = (v1 > 0.f) ? v1 : 0.01f * v1;
                const size_t base = (size_t)grow * NCOL + n0 + col;
                if (!PASS2) {
                    *(uint32_t*)&g_hq[base] =
                        (uint32_t)__half_as_ushort(__float2half_rn(v0)) |
                        ((uint32_t)__half_as_ushort(__float2half_rn(v1)) << 16);
                } else {
                    *(float2*)&g_out2[base] = make_float2(wgt * v0, wgt * v1);
                }
            }
        }
    }
}

// ---------------- combine (+ re-zero g_cnt for next invocation) ----------------
__global__ void combine_kernel(float* __restrict__ out) {
    const int t = blockIdx.x * blockDim.x + threadIdx.x;
    if (blockIdx.x == 0 && threadIdx.x < E_EXP) g_cnt[threadIdx.x] = 0;
    if (t >= N_TOK * (D_DIM / 4)) return;
    const int n = t / (D_DIM / 4);
    const int d = (t % (D_DIM / 4)) * 4;
    const int s0 = g_slot[2 * n], s1 = g_slot[2 * n + 1];
    float4 a = *(const float4*)(g_out2 + (size_t)s0 * D_DIM + d);
    float4 b = *(const float4*)(g_out2 + (size_t)s1 * D_DIM + d);
    float4 r; r.x = a.x + b.x; r.y = a.y + b.y; r.z = a.z + b.z; r.w = a.w + b.w;
    *(float4*)(out + (size_t)n * D_DIM + d) = r;
}

extern "C" void kernel_launch(void* const* d_in, const int* in_sizes, int n_in,
                              void* d_out, int out_size) {
    const float* x  = (const float*)d_in[0];
    const float* Wr = (const float*)d_in[1];
    const float* br = (const float*)d_in[2];
    const float* W1 = (const float*)d_in[3];
    const float* b1 = (const float*)d_in[4];
    const float* W2 = (const float*)d_in[5];
    const float* b2 = (const float*)d_in[6];
    float* out = (float*)d_out;

    constexpr int SMEM1 = 1024 + NSTAGE * (128 * ROWB + 128 * ROWB);  // 111616
    constexpr int SMEM2 = 1024 + NSTAGE * (64 * ROWB + 128 * ROWB);   // 83968
    cudaFuncSetAttribute(gemm_f16<false, D_DIM, H_DIM>,
                         cudaFuncAttributeMaxDynamicSharedMemorySize, SMEM1);
    cudaFuncSetAttribute(gemm_f16<true, H_DIM, D_DIM>,
                         cudaFuncAttributeMaxDynamicSharedMemorySize, SMEM2);

    // REAL device addresses of __device__ scratch (never pass symbols from host!)
    __half *w1q, *w2q;
    cudaGetSymbolAddress((void**)&w1q, g_w1q);
    cudaGetSymbolAddress((void**)&w2q, g_w2q);

    router_kernel<<<RBLK, 256>>>(x, Wr, br, out, out_size);
    transpose_both_kernel<<<dim3(32, 32, 2 * E_EXP), dim3(32, 8)>>>(W1, W2, w1q, w2q);
    gemm_f16<false, D_DIM, H_DIM>
        <<<dim3(H_DIM / BN, MAXT1, 1), 256, SMEM1>>>(b1);
    gemm_f16<true, H_DIM, D_DIM>
        <<<dim3(D_DIM / BN, MAXT2, 1), 256, SMEM2>>>(b2);
    combine_kernel<<<(N_TOK * D_DIM / 4 + 255) / 256, 256>>>(out);
}

// round 17
// speedup vs baseline: 1.0210x; 1.0210x over previous
#include <cuda_runtime.h>
#include <cuda_fp16.h>
#include <cstdint>

// Problem dims: B=8, T=2048 -> N=16384 tokens, D=512, E=8, H=1024, top_k=2
#define N_TOK   16384
#define D_DIM   512
#define E_EXP   8
#define H_DIM   1024
#define NPAIR   (2 * N_TOK)
#define RBLK    (N_TOK / 8)
#define CAP     N_TOK                 // fixed per-expert segment capacity
#define NROW    (E_EXP * CAP)

#define BN 128
#define KCH 64                       // 64 fp16 = 128B data per row per chunk
#define ROWB 144                     // smem row stride (128B data + 16B pad)
#define NSTAGE 3
#define MAXT1 264                    // pass1 tile grid (BM=128)
#define MAXT2 520                    // pass2 tile grid (BM=64)

// ---------------- scratch (static device globals) ----------------
__device__ __align__(1024) __half g_xq[(size_t)N_TOK * D_DIM];
__device__ __align__(1024) __half g_w1q[(size_t)E_EXP * H_DIM * D_DIM]; // [E][H][D] K-major
__device__ __align__(1024) __half g_w2q[(size_t)E_EXP * D_DIM * H_DIM]; // [E][D][H] K-major
__device__ __align__(1024) __half g_hq[(size_t)NROW * H_DIM];
__device__ __align__(1024) float g_out2[(size_t)NROW * D_DIM];
__device__ int   g_tok[NROW];
__device__ float g_w[NROW];
__device__ int   g_slot[NPAIR];
__device__ int   g_cnt[E_EXP];                   // zeroed at load; re-zeroed by combine tail
__device__ int   g_toff1[E_EXP + 1];             // tile prefix, BM=128 (pass1)
__device__ int   g_toff2[E_EXP + 1];             // tile prefix, BM=64  (pass2)
__device__ float g_psums[RBLK * E_EXP];

// ---------------- PTX helpers (baseline ISA only) ----------------
__device__ __forceinline__ uint32_t smem_u32(const void* p) {
    uint32_t a;
    asm("{ .reg .u64 t; cvta.to.shared.u64 t, %1; cvt.u32.u64 %0, t; }" : "=r"(a) : "l"(p));
    return a;
}
__device__ __forceinline__ void cp16(uint32_t dst, const void* src) {
    asm volatile("cp.async.cg.shared.global [%0], [%1], 16;" :: "r"(dst), "l"(src));
}
__device__ __forceinline__ void ldsm4(uint32_t* r, uint32_t addr) {
    asm volatile("ldmatrix.sync.aligned.m8n8.x4.shared.b16 {%0,%1,%2,%3}, [%4];"
                 : "=r"(r[0]), "=r"(r[1]), "=r"(r[2]), "=r"(r[3]) : "r"(addr));
}
__device__ __forceinline__ void mma_f16(float* c, const uint32_t* a, uint32_t b0, uint32_t b1) {
    asm volatile(
        "mma.sync.aligned.m16n8k16.row.col.f32.f16.f16.f32 "
        "{%0,%1,%2,%3}, {%4,%5,%6,%7}, {%8,%9}, {%0,%1,%2,%3};"
        : "+f"(c[0]), "+f"(c[1]), "+f"(c[2]), "+f"(c[3])
        : "r"(a[0]), "r"(a[1]), "r"(a[2]), "r"(a[3]), "r"(b0), "r"(b1));
}

// ---------------- router (R14-proven: logits + softmax + top2 + scatter + x->fp16) ----------------
__global__ void router_kernel(const float* __restrict__ x,
                              const float* __restrict__ Wr,
                              const float* __restrict__ br) {
    __shared__ float ps[8][E_EXP];
    const int wid = threadIdx.x >> 5, lane = threadIdx.x & 31;
    const int n = blockIdx.x * 8 + wid;
    const float* xr = x + (size_t)n * D_DIM;
    __half* xq = g_xq + (size_t)n * D_DIM;
    float acc[E_EXP];
#pragma unroll
    for (int e = 0; e < E_EXP; e++) acc[e] = 0.f;
    for (int i = lane; i < D_DIM; i += 32) {       // coalesced on x
        float xv = xr[i];
        xq[i] = __float2half_rn(xv);
        const float* w = Wr + i * E_EXP;
#pragma unroll
        for (int e = 0; e < E_EXP; e++) acc[e] += xv * w[e];
    }
#pragma unroll
    for (int e = 0; e < E_EXP; e++)
#pragma unroll
        for (int o = 16; o > 0; o >>= 1)
            acc[e] += __shfl_xor_sync(0xffffffffu, acc[e], o);

    if (lane == 0) {
        float mx = -1e30f;
#pragma unroll
        for (int e = 0; e < E_EXP; e++) { acc[e] += br[e]; mx = fmaxf(mx, acc[e]); }
        float s = 0.f;
#pragma unroll
        for (int e = 0; e < E_EXP; e++) { acc[e] = expf(acc[e] - mx); s += acc[e]; }
        const float inv = 1.f / s;
        float p1 = -1.f, p2 = -1.f; int i1 = 0, i2 = 0;
#pragma unroll
        for (int e = 0; e < E_EXP; e++) {
            float p = acc[e] * inv;
            ps[wid][e] = p;
            if (p > p1)      { p2 = p1; i2 = i1; p1 = p; i1 = e; }
            else if (p > p2) { p2 = p; i2 = e; }
        }
        int pos1 = atomicAdd(&g_cnt[i1], 1);
        int p1i = i1 * CAP + pos1;
        g_tok[p1i] = n; g_w[p1i] = p1; g_slot[2 * n] = p1i;
        int pos2 = atomicAdd(&g_cnt[i2], 1);
        int p2i = i2 * CAP + pos2;
        g_tok[p2i] = n; g_w[p2i] = p2; g_slot[2 * n + 1] = p2i;
    }
    __syncthreads();
    if (threadIdx.x < E_EXP) {
        float s = 0.f;
#pragma unroll
        for (int w = 0; w < 8; w++) s += ps[w][threadIdx.x];
        g_psums[blockIdx.x * E_EXP + threadIdx.x] = s;
    }
}

// ---------------- tile prefixes (both BM) + gating loss ----------------
__global__ void offsets_loss_kernel(float* __restrict__ out, int out_size) {
    __shared__ float dsq[E_EXP];
    const int tid = threadIdx.x;
    if (tid == 0) {
        int t1 = 0, t2 = 0;
        for (int e = 0; e < E_EXP; e++) {
            g_toff1[e] = t1;
            g_toff2[e] = t2;
            int c = g_cnt[e];
            t1 += (c + 127) >> 7;
            t2 += (c + 63) >> 6;
        }
        g_toff1[E_EXP] = t1;
        g_toff2[E_EXP] = t2;
    }
    const int wid = tid >> 5, lane = tid & 31;
    if (wid < E_EXP) {
        float s = 0.f;
        for (int b = lane; b < RBLK; b += 32) s += g_psums[b * E_EXP + wid];
#pragma unroll
        for (int o = 16; o > 0; o >>= 1) s += __shfl_xor_sync(0xffffffffu, s, o);
        if (lane == 0) {
            float mean = s / (float)N_TOK;
            float d = (1.0f / E_EXP) - mean;
            dsq[wid] = d * d;
        }
    }
    __syncthreads();
    if (tid == 0 && out_size > N_TOK * D_DIM) {
        float l = 0.f;
        for (int e = 0; e < E_EXP; e++) l += dsq[e];
        out[N_TOK * D_DIM] = (l / E_EXP) * 1e-4f;
    }
}

// ---------------- merged weight transpose (real device addrs only — ATS trap) ----------------
__global__ void transpose_both_kernel(const float* __restrict__ W1,
                                      const float* __restrict__ W2,
                                      __half* __restrict__ T1,
                                      __half* __restrict__ T2) {
    __shared__ float t[32][33];
    const int z = blockIdx.z;
    const bool isW2 = (z >= E_EXP);
    const int e = z & (E_EXP - 1);
    const int K = isW2 ? H_DIM : D_DIM;
    const int N = isW2 ? D_DIM : H_DIM;
    const float* W = isW2 ? W2 : W1;
    __half* T = isW2 ? T2 : T1;
    const int n0 = blockIdx.x * 32, k0 = blockIdx.y * 32;
    if (n0 >= N || k0 >= K) return;
    const int tx = threadIdx.x, ty = threadIdx.y;
    for (int i = ty; i < 32; i += 8)
        t[i][tx] = W[((size_t)e * K + k0 + i) * N + n0 + tx];
    __syncthreads();
    for (int i = ty; i < 32; i += 8) {
        float v = t[tx][i];
        T[((size_t)e * N + n0 + i) * K + k0 + tx] = __float2half_rn(v);
    }
}

// ---------------- fp16 GEMM via mma.m16n8k16 + ldmatrix ----------------
// PASS2=false: BM=128, h = leaky(gather(xq)@W1q^T + b1) -> g_hq,   KDIM=512,  NCOL=1024
// PASS2=true : BM=64,  o = w*leaky(hq@W2q^T + b2)       -> g_out2, KDIM=1024, NCOL=512
template <bool PASS2, int KDIM, int NCOL>
__global__ void __launch_bounds__(256, 2)
gemm_f16(const float* __restrict__ bias) {
    constexpr int BMT = PASS2 ? 64 : 128;        // m-tile
    constexpr int MH  = BMT / 2;                 // rows per warp_m
    constexpr int AF  = MH / 16;                 // a-frags per warp (4 / 2)
    constexpr int AU  = BMT * 8 / 256;           // A cp.async units/thread (4 / 2)
    constexpr int TILE_A = BMT * ROWB;
    constexpr int TILE_B = BN * ROWB;
    constexpr int STG = TILE_A + TILE_B;

    extern __shared__ char smem[];
    const int* toff = PASS2 ? g_toff2 : g_toff1;
    const int ty = blockIdx.y;
    if (ty >= toff[E_EXP]) return;
    int e = 0;
#pragma unroll
    for (int i = 1; i < E_EXP; i++) if (ty >= toff[i]) e = i;
    const int cnt = g_cnt[e];
    const int m0 = (ty - toff[e]) * BMT;
    const int n0 = blockIdx.x * BN;
    const int off = e * CAP;
    const int tid = threadIdx.x;
    const int wid = tid >> 5, lane = tid & 31;
    const int warp_m = wid >> 2;                 // 0..1
    const int warp_n = wid & 3;                  // 0..3 (32 cols each)
    const int qr = lane >> 2;
    const int qc = (lane & 3) * 2;

    const uint32_t sbase = smem_u32(smem);
    int* toks = (int*)smem;                      // [0,512)
    const uint32_t TILE0 = 1024;

    if (!PASS2) {
        if (tid < BMT) {
            int m = m0 + tid;
            toks[tid] = g_tok[off + (m < cnt ? m : cnt - 1)];
        }
        __syncthreads();
    }

    const char* Aqb = (const char*)(PASS2 ? g_hq : g_xq);
    const char* Bqb = (const char*)(PASS2 ? g_w2q : g_w1q);

    // cp.async plan
    size_t aoff[AU], boff[4];
    uint32_t adst[AU], bdst[4];
#pragma unroll
    for (int t = 0; t < AU; t++) {
        int uu = tid + 256 * t;
        int r = uu >> 3, u = uu & 7;
        adst[t] = (uint32_t)(r * ROWB + u * 16);
        if (!PASS2) {
            aoff[t] = ((size_t)toks[r] * KDIM) * 2 + u * 16;
        } else {
            int m = m0 + r;
            int row = off + (m < cnt ? m : cnt - 1);
            aoff[t] = ((size_t)row * KDIM) * 2 + u * 16;
        }
    }
#pragma unroll
    for (int t = 0; t < 4; t++) {
        int uu = tid + 256 * t;
        int r = uu >> 3, u = uu & 7;
        bdst[t] = (uint32_t)(r * ROWB + u * 16);
        boff[t] = ((size_t)(e * NCOL + n0 + r) * KDIM) * 2 + u * 16;
    }

    auto issue_loads = [&](int c, int s) {
        const uint32_t st = sbase + TILE0 + s * STG;
        const size_t kb = (size_t)c * (KCH * 2);
#pragma unroll
        for (int t = 0; t < AU; t++)
            cp16(st + adst[t], Aqb + aoff[t] + kb);
#pragma unroll
        for (int t = 0; t < 4; t++)
            cp16(st + TILE_A + bdst[t], Bqb + boff[t] + kb);
        asm volatile("cp.async.commit_group;" ::: "memory");
    };

    float acc[AF][4][4];
#pragma unroll
    for (int f = 0; f < AF; f++)
#pragma unroll
        for (int g = 0; g < 4; g++)
#pragma unroll
            for (int q = 0; q < 4; q++) acc[f][g][q] = 0.f;

    constexpr int C = KDIM / KCH;
    issue_loads(0, 0);
    issue_loads(1, 1);

    uint32_t aBase[AF];
#pragma unroll
    for (int f = 0; f < AF; f++)
        aBase[f] = (uint32_t)((warp_m * MH + f * 16 + (lane & 15)) * ROWB + (lane >> 4) * 16);
    uint32_t bBase[2];
#pragma unroll
    for (int p = 0; p < 2; p++)
        bBase[p] = (uint32_t)((warp_n * 32 + p * 16 + ((lane >> 4) & 1) * 8 + (lane & 7)) * ROWB
                              + ((lane >> 3) & 1) * 16);

    for (int c = 0; c < C; c++) {
        const int s = c % NSTAGE;
        if (c == C - 1) asm volatile("cp.async.wait_group 0;" ::: "memory");
        else            asm volatile("cp.async.wait_group 1;" ::: "memory");
        __syncthreads();                         // single barrier per chunk
        if (c + 2 < C) issue_loads(c + 2, (c + 2) % NSTAGE);

        const uint32_t stA = sbase + TILE0 + s * STG;
        const uint32_t stB = stA + TILE_A;

#pragma unroll
        for (int ks = 0; ks < 4; ks++) {
            const uint32_t ko = (uint32_t)(ks * 32);
            uint32_t aq[AF][4], bq[2][4];
#pragma unroll
            for (int f = 0; f < AF; f++) ldsm4(aq[f], stA + aBase[f] + ko);
#pragma unroll
            for (int p = 0; p < 2; p++) ldsm4(bq[p], stB + bBase[p] + ko);
#pragma unroll
            for (int f = 0; f < AF; f++)
#pragma unroll
                for (int p = 0; p < 2; p++) {
                    mma_f16(acc[f][2 * p],     aq[f], bq[p][0], bq[p][1]);
                    mma_f16(acc[f][2 * p + 1], aq[f], bq[p][2], bq[p][3]);
                }
        }
    }

    // ---- epilogue ----
    const float* bb = bias + e * NCOL + n0;
#pragma unroll
    for (int f = 0; f < AF; f++) {
        const int rbase = warp_m * MH + f * 16 + qr;
#pragma unroll
        for (int half = 0; half < 2; half++) {
            const int row = rbase + half * 8;
            const int m = m0 + row;
            if (m >= cnt) continue;
            const int grow = off + m;
            float wgt = 0.f;
            if (PASS2) wgt = g_w[grow];
#pragma unroll
            for (int g = 0; g < 4; g++) {
                const int col = warp_n * 32 + g * 8 + qc;
                float v0 = acc[f][g][2 * half + 0] + bb[col];
                float v1 = acc[f][g][2 * half + 1] + bb[col + 1];
                v0 = (v0 > 0.f) ? v0 : 0.01f * v0;
                v1 = (v1 > 0.f) ? v1 : 0.01f * v1;
                const size_t base = (size_t)grow * NCOL + n0 + col;
                if (!PASS2) {
                    *(uint32_t*)&g_hq[base] =
                        (uint32_t)__half_as_ushort(__float2half_rn(v0)) |
                        ((uint32_t)__half_as_ushort(__float2half_rn(v1)) << 16);
                } else {
                    *(float2*)&g_out2[base] = make_float2(wgt * v0, wgt * v1);
                }
            }
        }
    }
}

// ---------------- combine (+ re-zero g_cnt for next invocation) ----------------
__global__ void combine_kernel(float* __restrict__ out) {
    const int t = blockIdx.x * blockDim.x + threadIdx.x;
    if (blockIdx.x == 0 && threadIdx.x < E_EXP) g_cnt[threadIdx.x] = 0;
    if (t >= N_TOK * (D_DIM / 4)) return;
    const int n = t / (D_DIM / 4);
    const int d = (t % (D_DIM / 4)) * 4;
    const int s0 = g_slot[2 * n], s1 = g_slot[2 * n + 1];
    float4 a = *(const float4*)(g_out2 + (size_t)s0 * D_DIM + d);
    float4 b = *(const float4*)(g_out2 + (size_t)s1 * D_DIM + d);
    float4 r; r.x = a.x + b.x; r.y = a.y + b.y; r.z = a.z + b.z; r.w = a.w + b.w;
    *(float4*)(out + (size_t)n * D_DIM + d) = r;
}

extern "C" void kernel_launch(void* const* d_in, const int* in_sizes, int n_in,
                              void* d_out, int out_size) {
    const float* x  = (const float*)d_in[0];
    const float* Wr = (const float*)d_in[1];
    const float* br = (const float*)d_in[2];
    const float* W1 = (const float*)d_in[3];
    const float* b1 = (const float*)d_in[4];
    const float* W2 = (const float*)d_in[5];
    const float* b2 = (const float*)d_in[6];
    float* out = (float*)d_out;

    constexpr int SMEM1 = 1024 + NSTAGE * (128 * ROWB + 128 * ROWB);  // 111616
    constexpr int SMEM2 = 1024 + NSTAGE * (64 * ROWB + 128 * ROWB);   // 83968
    cudaFuncSetAttribute(gemm_f16<false, D_DIM, H_DIM>,
                         cudaFuncAttributeMaxDynamicSharedMemorySize, SMEM1);
    cudaFuncSetAttribute(gemm_f16<true, H_DIM, D_DIM>,
                         cudaFuncAttributeMaxDynamicSharedMemorySize, SMEM2);

    // REAL device addresses of __device__ scratch (never pass symbols from host!)
    __half *w1q, *w2q;
    cudaGetSymbolAddress((void**)&w1q, g_w1q);
    cudaGetSymbolAddress((void**)&w2q, g_w2q);

    router_kernel<<<RBLK, 256>>>(x, Wr, br);
    offsets_loss_kernel<<<1, 256>>>(out, out_size);
    transpose_both_kernel<<<dim3(32, 32, 2 * E_EXP), dim3(32, 8)>>>(W1, W2, w1q, w2q);
    gemm_f16<false, D_DIM, H_DIM>
        <<<dim3(H_DIM / BN, MAXT1, 1), 256, SMEM1>>>(b1);
    gemm_f16<true, H_DIM, D_DIM>
        <<<dim3(D_DIM / BN, MAXT2, 1), 256, SMEM2>>>(b2);
    combine_kernel<<<(N_TOK * D_DIM / 4 + 255) / 256, 256>>>(out);
}